// round 1
// baseline (speedup 1.0000x reference)
#include <cuda_runtime.h>
#include <math.h>

#define N_NODES 50000
#define N_EDGES 800000
#define IN_DIM  128
#define HID_DIM 128
#define OUT_DIM 64

// ---------------- scratch (static device globals; no allocation) ----------------
__device__ float g_deg [N_NODES];
__device__ float g_dinv[N_NODES];
__device__ float g_h   [(size_t)N_NODES * HID_DIM];  // x @ W1 (raw, pre-norm)
__device__ float g_h2  [(size_t)N_NODES * OUT_DIM];  // h1 @ W2 (raw, pre-norm)
__device__ float g_Wt1 [IN_DIM  * HID_DIM];          // W1^T  [j][k]
__device__ float g_Wt2 [HID_DIM * OUT_DIM];          // W2^T  [j][k]

// ---------------- degree / norm ----------------
__global__ void k_deg_init() {
    int i = blockIdx.x * blockDim.x + threadIdx.x;
    if (i < N_NODES) g_deg[i] = 1.0f;  // self-loop
}

__global__ void k_deg_count(const int* __restrict__ dst) {
    int e = blockIdx.x * blockDim.x + threadIdx.x;
    if (e < N_EDGES) atomicAdd(&g_deg[dst[e]], 1.0f);
}

__global__ void k_dinv() {
    int i = blockIdx.x * blockDim.x + threadIdx.x;
    if (i < N_NODES) g_dinv[i] = rsqrtf(g_deg[i]);
}

// ---------------- W transpose (once per call, tiny) ----------------
__global__ void k_transpose(const float* __restrict__ W, float* __restrict__ Wt,
                            int K, int Ncol) {
    int idx = blockIdx.x * blockDim.x + threadIdx.x;
    if (idx < K * Ncol) {
        int k = idx / Ncol;
        int j = idx % Ncol;
        Wt[j * K + k] = W[idx];
    }
}

// ---------------- GEMM: Y[n,NCOLS] = X[n,KDIM] @ W[KDIM,NCOLS] via Wt ----------------
// blockDim = NCOLS threads, each block does ROWS rows; thread j owns column j.
template <int KDIM, int NCOLS, int ROWS>
__global__ void k_gemm(const float* __restrict__ X, const float* __restrict__ Wt,
                       float* __restrict__ Y) {
    __shared__ float xs[ROWS * KDIM];
    const int j  = threadIdx.x;
    const int r0 = blockIdx.x * ROWS;

    // cooperative float4 load of the X tile
    const float4* xg  = (const float4*)(X + (size_t)r0 * KDIM);
    float4*       xsv = (float4*)xs;
    const int total4 = ROWS * KDIM / 4;
    for (int t = j; t < total4; t += NCOLS) xsv[t] = xg[t];
    __syncthreads();

    float acc[ROWS];
#pragma unroll
    for (int r = 0; r < ROWS; r++) acc[r] = 0.0f;

    const float4* wv = (const float4*)(Wt + (size_t)j * KDIM);
#pragma unroll 8
    for (int k4 = 0; k4 < KDIM / 4; k4++) {
        float4 w = wv[k4];
#pragma unroll
        for (int r = 0; r < ROWS; r++) {
            float4 xv = ((const float4*)(xs + r * KDIM))[k4];
            acc[r] += xv.x * w.x + xv.y * w.y + xv.z * w.z + xv.w * w.w;
        }
    }

#pragma unroll
    for (int r = 0; r < ROWS; r++)
        Y[(size_t)(r0 + r) * NCOLS + j] = acc[r];
}

// ---------------- out init: self-loop + bias ----------------
// out[i*C+c] = hraw[i*C+c] * dinv[i]^2 + b[c]
__global__ void k_init_out(const float* __restrict__ hraw, const float* __restrict__ b,
                           float* __restrict__ out, int C, int total) {
    int idx = blockIdx.x * blockDim.x + threadIdx.x;
    if (idx < total) {
        int i = idx / C;
        int c = idx - i * C;
        float di = g_dinv[i];
        out[idx] = hraw[idx] * di * di + b[c];
    }
}

// ---------------- edge scatter: warp per edge, coalesced atomics ----------------
template <int C>
__global__ void k_scatter(const int* __restrict__ src, const int* __restrict__ dst,
                          const float* __restrict__ hraw, float* __restrict__ out) {
    int t = blockIdx.x * blockDim.x + threadIdx.x;
    int e = t >> 5;
    if (e >= N_EDGES) return;
    int lane = t & 31;
    int s = src[e];
    int d = dst[e];
    float nrm = g_dinv[s] * g_dinv[d];
    const float* hp = hraw + (size_t)s * C;
    float*       op = out  + (size_t)d * C;
#pragma unroll
    for (int i = 0; i < C / 32; i++) {
        int c = lane + 32 * i;
        atomicAdd(op + c, hp[c] * nrm);  // unused return -> RED.E.ADD.F32, coalesced
    }
}

// ---------------- ReLU in place ----------------
__global__ void k_relu(float* __restrict__ p, int total) {
    int idx = blockIdx.x * blockDim.x + threadIdx.x;
    if (idx < total) p[idx] = fmaxf(p[idx], 0.0f);
}

// ---------------- launch ----------------
extern "C" void kernel_launch(void* const* d_in, const int* in_sizes, int n_in,
                              void* d_out, int out_size) {
    const float* x  = (const float*)d_in[0];
    const int*   ei = (const int*)  d_in[1];
    const float* W1 = (const float*)d_in[2];
    const float* b1 = (const float*)d_in[3];
    const float* W2 = (const float*)d_in[4];
    const float* b2 = (const float*)d_in[5];

    const int* src = ei;
    const int* dst = ei + N_EDGES;

    float* out_h2 = (float*)d_out;                                  // [N, 64]
    float* out_h1 = out_h2 + (size_t)N_NODES * OUT_DIM;             // [N, 128]

    void *p_h, *p_h2, *p_wt1, *p_wt2;
    cudaGetSymbolAddress(&p_h,   g_h);
    cudaGetSymbolAddress(&p_h2,  g_h2);
    cudaGetSymbolAddress(&p_wt1, g_Wt1);
    cudaGetSymbolAddress(&p_wt2, g_Wt2);
    float* hbuf  = (float*)p_h;
    float* h2buf = (float*)p_h2;
    float* wt1   = (float*)p_wt1;
    float* wt2   = (float*)p_wt2;

    const int TB = 256;

    // degrees + normalization
    k_deg_init <<<(N_NODES + TB - 1) / TB, TB>>>();
    k_deg_count<<<(N_EDGES + TB - 1) / TB, TB>>>(dst);
    k_dinv     <<<(N_NODES + TB - 1) / TB, TB>>>();

    // weight transposes
    k_transpose<<<(IN_DIM * HID_DIM + TB - 1) / TB, TB>>>(W1, wt1, IN_DIM, HID_DIM);
    k_transpose<<<(HID_DIM * OUT_DIM + TB - 1) / TB, TB>>>(W2, wt2, HID_DIM, OUT_DIM);

    // ---- layer 1 ----
    k_gemm<IN_DIM, HID_DIM, 8><<<N_NODES / 8, HID_DIM>>>(x, wt1, hbuf);

    int tot1 = N_NODES * HID_DIM;
    k_init_out<<<(tot1 + TB - 1) / TB, TB>>>(hbuf, b1, out_h1, HID_DIM, tot1);
    k_scatter<HID_DIM><<<(N_EDGES * 32) / TB, TB>>>(src, dst, hbuf, out_h1);
    k_relu<<<(tot1 + TB - 1) / TB, TB>>>(out_h1, tot1);

    // ---- layer 2 ----
    k_gemm<HID_DIM, OUT_DIM, 8><<<N_NODES / 8, OUT_DIM>>>(out_h1, wt2, h2buf);

    int tot2 = N_NODES * OUT_DIM;
    k_init_out<<<(tot2 + TB - 1) / TB, TB>>>(h2buf, b2, out_h2, OUT_DIM, tot2);
    k_scatter<OUT_DIM><<<(N_EDGES * 32) / TB, TB>>>(src, dst, h2buf, out_h2);
}

// round 2
// speedup vs baseline: 1.1598x; 1.1598x over previous
#include <cuda_runtime.h>
#include <math.h>

#define N_NODES 50000
#define N_EDGES 800000
#define IN_DIM  128
#define HID_DIM 128
#define OUT_DIM 64

// ---------------- scratch (static device globals; no allocation) ----------------
__device__ float g_deg [N_NODES];
__device__ float g_dinv[N_NODES];
__device__ float g_h   [(size_t)N_NODES * HID_DIM];  // x @ W1 (raw, pre-norm)
__device__ float g_h2  [(size_t)N_NODES * OUT_DIM];  // h1 @ W2 (raw, pre-norm)
__device__ float g_Wt1 [IN_DIM  * HID_DIM];          // W1^T  [j][k]
__device__ float g_Wt2 [HID_DIM * OUT_DIM];          // W2^T  [j][k]

// ---------------- degree / norm ----------------
__global__ void k_deg_init() {
    int i = blockIdx.x * blockDim.x + threadIdx.x;
    if (i < N_NODES) g_deg[i] = 1.0f;  // self-loop
}

__global__ void k_deg_count(const int* __restrict__ dst) {
    int e = blockIdx.x * blockDim.x + threadIdx.x;
    if (e < N_EDGES) atomicAdd(&g_deg[dst[e]], 1.0f);
}

__global__ void k_dinv() {
    int i = blockIdx.x * blockDim.x + threadIdx.x;
    if (i < N_NODES) g_dinv[i] = rsqrtf(g_deg[i]);
}

// ---------------- W transpose (once per call, tiny) ----------------
__global__ void k_transpose(const float* __restrict__ W, float* __restrict__ Wt,
                            int K, int Ncol) {
    int idx = blockIdx.x * blockDim.x + threadIdx.x;
    if (idx < K * Ncol) {
        int k = idx / Ncol;
        int j = idx % Ncol;
        Wt[j * K + k] = W[idx];
    }
}

// ---------------- GEMM with fused self-loop/bias epilogue ----------------
// Y[n,NCOLS] = X @ W. Writes raw result to Yraw, and out = acc*dinv[row]^2 + b.
template <int KDIM, int NCOLS, int ROWS>
__global__ void k_gemm_fused(const float* __restrict__ X, const float* __restrict__ Wt,
                             const float* __restrict__ b,
                             float* __restrict__ Yraw, float* __restrict__ Yout) {
    __shared__ float xs[ROWS * KDIM];
    const int j  = threadIdx.x;
    const int r0 = blockIdx.x * ROWS;

    // cooperative float4 load of the X tile
    const float4* xg  = (const float4*)(X + (size_t)r0 * KDIM);
    float4*       xsv = (float4*)xs;
    const int total4 = ROWS * KDIM / 4;
    for (int t = j; t < total4; t += NCOLS) xsv[t] = xg[t];
    __syncthreads();

    float acc[ROWS];
#pragma unroll
    for (int r = 0; r < ROWS; r++) acc[r] = 0.0f;

    const float4* wv = (const float4*)(Wt + (size_t)j * KDIM);
#pragma unroll 8
    for (int k4 = 0; k4 < KDIM / 4; k4++) {
        float4 w = wv[k4];
#pragma unroll
        for (int r = 0; r < ROWS; r++) {
            float4 xv = ((const float4*)(xs + r * KDIM))[k4];
            acc[r] += xv.x * w.x + xv.y * w.y + xv.z * w.z + xv.w * w.w;
        }
    }

    float bj = b[j];
#pragma unroll
    for (int r = 0; r < ROWS; r++) {
        int   row = r0 + r;
        float di  = g_dinv[row];
        Yraw[(size_t)row * NCOLS + j] = acc[r];
        Yout[(size_t)row * NCOLS + j] = acc[r] * di * di + bj;
    }
}

// ---------------- vectorized red.global.add.v4.f32 ----------------
__device__ __forceinline__ void red_add_v4(float* ptr, float4 v) {
    asm volatile("red.global.add.v4.f32 [%0], {%1, %2, %3, %4};"
                 :: "l"(ptr), "f"(v.x), "f"(v.y), "f"(v.z), "f"(v.w)
                 : "memory");
}

// ---------------- edge scatter, C=128: warp per edge, lane -> one float4 ----------------
__global__ void k_scatter128(const int* __restrict__ src, const int* __restrict__ dst,
                             const float* __restrict__ hraw, float* __restrict__ out) {
    int t = blockIdx.x * blockDim.x + threadIdx.x;
    int e = t >> 5;
    if (e >= N_EDGES) return;
    int lane = t & 31;
    int s = src[e];
    int d = dst[e];
    float nrm = g_dinv[s] * g_dinv[d];
    float4 h = __ldg((const float4*)(hraw + (size_t)s * 128) + lane);
    h.x *= nrm; h.y *= nrm; h.z *= nrm; h.w *= nrm;
    red_add_v4((float*)((float4*)(out + (size_t)d * 128) + lane), h);
}

// ---------------- edge scatter, C=64: half-warp per edge ----------------
__global__ void k_scatter64(const int* __restrict__ src, const int* __restrict__ dst,
                            const float* __restrict__ hraw, float* __restrict__ out) {
    int t = blockIdx.x * blockDim.x + threadIdx.x;
    int lane = t & 31;
    int e = ((t >> 5) << 1) + (lane >> 4);   // 2 edges per warp
    if (e >= N_EDGES) return;
    int l4 = lane & 15;                      // 16 lanes x float4 = 64 floats
    int s = src[e];
    int d = dst[e];
    float nrm = g_dinv[s] * g_dinv[d];
    float4 h = __ldg((const float4*)(hraw + (size_t)s * 64) + l4);
    h.x *= nrm; h.y *= nrm; h.z *= nrm; h.w *= nrm;
    red_add_v4((float*)((float4*)(out + (size_t)d * 64) + l4), h);
}

// ---------------- ReLU in place (float4) ----------------
__global__ void k_relu4(float4* __restrict__ p, int total4) {
    int idx = blockIdx.x * blockDim.x + threadIdx.x;
    if (idx < total4) {
        float4 v = p[idx];
        v.x = fmaxf(v.x, 0.0f);
        v.y = fmaxf(v.y, 0.0f);
        v.z = fmaxf(v.z, 0.0f);
        v.w = fmaxf(v.w, 0.0f);
        p[idx] = v;
    }
}

// ---------------- launch ----------------
extern "C" void kernel_launch(void* const* d_in, const int* in_sizes, int n_in,
                              void* d_out, int out_size) {
    const float* x  = (const float*)d_in[0];
    const int*   ei = (const int*)  d_in[1];
    const float* W1 = (const float*)d_in[2];
    const float* b1 = (const float*)d_in[3];
    const float* W2 = (const float*)d_in[4];
    const float* b2 = (const float*)d_in[5];

    const int* src = ei;
    const int* dst = ei + N_EDGES;

    float* out_h2 = (float*)d_out;                                  // [N, 64]
    float* out_h1 = out_h2 + (size_t)N_NODES * OUT_DIM;             // [N, 128]

    void *p_h, *p_h2, *p_wt1, *p_wt2;
    cudaGetSymbolAddress(&p_h,   g_h);
    cudaGetSymbolAddress(&p_h2,  g_h2);
    cudaGetSymbolAddress(&p_wt1, g_Wt1);
    cudaGetSymbolAddress(&p_wt2, g_Wt2);
    float* hbuf  = (float*)p_h;
    float* h2buf = (float*)p_h2;
    float* wt1   = (float*)p_wt1;
    float* wt2   = (float*)p_wt2;

    const int TB = 256;

    // degrees + normalization (must precede the fused GEMMs)
    k_deg_init <<<(N_NODES + TB - 1) / TB, TB>>>();
    k_deg_count<<<(N_EDGES + TB - 1) / TB, TB>>>(dst);
    k_dinv     <<<(N_NODES + TB - 1) / TB, TB>>>();

    // weight transposes
    k_transpose<<<(IN_DIM * HID_DIM + TB - 1) / TB, TB>>>(W1, wt1, IN_DIM, HID_DIM);
    k_transpose<<<(HID_DIM * OUT_DIM + TB - 1) / TB, TB>>>(W2, wt2, HID_DIM, OUT_DIM);

    // ---- layer 1: GEMM (+fused self-loop/bias) -> scatter -> ReLU ----
    k_gemm_fused<IN_DIM, HID_DIM, 8><<<N_NODES / 8, HID_DIM>>>(x, wt1, b1, hbuf, out_h1);
    k_scatter128<<<(N_EDGES * 32 + TB - 1) / TB, TB>>>(src, dst, hbuf, out_h1);
    int tot1_4 = N_NODES * HID_DIM / 4;
    k_relu4<<<(tot1_4 + TB - 1) / TB, TB>>>((float4*)out_h1, tot1_4);

    // ---- layer 2: GEMM (+fused self-loop/bias) -> scatter ----
    k_gemm_fused<HID_DIM, OUT_DIM, 8><<<N_NODES / 8, OUT_DIM>>>(out_h1, wt2, b2, h2buf, out_h2);
    k_scatter64<<<(N_EDGES * 16 + TB - 1) / TB, TB>>>(src, dst, h2buf, out_h2);
}

// round 3
// speedup vs baseline: 2.4861x; 2.1436x over previous
#include <cuda_runtime.h>
#include <math.h>

#define N_NODES 50000
#define N_EDGES 800000
#define IN_DIM  128
#define HID_DIM 128
#define OUT_DIM 64

typedef unsigned long long ull;

// ---------------- scratch (static device globals; no allocation) ----------------
__device__ float g_dinv[N_NODES];
__device__ int   g_degi[N_NODES];
__device__ int   g_off [N_NODES + 1];
__device__ int   g_cur [N_NODES];
__device__ int   g_bsum[256];
__device__ int   g_col [N_EDGES];
__device__ float g_h   [(size_t)N_NODES * HID_DIM];  // x @ W1 (raw)
__device__ float g_h2  [(size_t)N_NODES * OUT_DIM];  // h1 @ W2 (raw)

// ---------------- f32x2 packed math ----------------
__device__ __forceinline__ ull pack2(float lo, float hi) {
    ull r; asm("mov.b64 %0, {%1, %2};" : "=l"(r) : "f"(lo), "f"(hi)); return r;
}
__device__ __forceinline__ ull fma2(ull a, ull b, ull c) {
    ull d; asm("fma.rn.f32x2 %0, %1, %2, %3;" : "=l"(d) : "l"(a), "l"(b), "l"(c)); return d;
}
__device__ __forceinline__ float2 unpack2(ull p) {
    float2 f; asm("mov.b64 {%0, %1}, %2;" : "=f"(f.x), "=f"(f.y) : "l"(p)); return f;
}

// ---------------- degree / norm ----------------
__global__ void k_zero() {
    int i = blockIdx.x * blockDim.x + threadIdx.x;
    if (i < N_NODES) g_degi[i] = 0;
}
__global__ void k_count(const int* __restrict__ dst) {
    int e = blockIdx.x * blockDim.x + threadIdx.x;
    if (e < N_EDGES) atomicAdd(&g_degi[dst[e]], 1);
}
__global__ void k_dinv() {
    int i = blockIdx.x * blockDim.x + threadIdx.x;
    if (i < N_NODES) g_dinv[i] = rsqrtf((float)(g_degi[i] + 1));  // +1 self-loop
}

// ---------------- exclusive scan (3 kernels, 50k elements) ----------------
__global__ void k_scan1() {
    __shared__ int s[256];
    int i = blockIdx.x * 256 + threadIdx.x;
    int v = (i < N_NODES) ? g_degi[i] : 0;
    s[threadIdx.x] = v;
    __syncthreads();
    for (int d = 1; d < 256; d <<= 1) {
        int t = (threadIdx.x >= d) ? s[threadIdx.x - d] : 0;
        __syncthreads();
        s[threadIdx.x] += t;
        __syncthreads();
    }
    if (i < N_NODES) g_off[i] = s[threadIdx.x] - v;     // exclusive within block
    if (threadIdx.x == 255) g_bsum[blockIdx.x] = s[255];
}
__global__ void k_scan2(int nblk) {
    __shared__ int s[256];
    int t = threadIdx.x;
    int v = (t < nblk) ? g_bsum[t] : 0;
    s[t] = v;
    __syncthreads();
    for (int d = 1; d < 256; d <<= 1) {
        int u = (t >= d) ? s[t - d] : 0;
        __syncthreads();
        s[t] += u;
        __syncthreads();
    }
    if (t < nblk) g_bsum[t] = s[t] - v;                 // exclusive
}
__global__ void k_scan3() {
    int i = blockIdx.x * blockDim.x + threadIdx.x;
    if (i < N_NODES) {
        int o = g_off[i] + g_bsum[i >> 8];
        g_off[i] = o;
        g_cur[i] = o;
    }
    if (i == 0) g_off[N_NODES] = N_EDGES;
}
__global__ void k_fill(const int* __restrict__ src, const int* __restrict__ dst) {
    int e = blockIdx.x * blockDim.x + threadIdx.x;
    if (e < N_EDGES) {
        int p = atomicAdd(&g_cur[dst[e]], 1);
        g_col[p] = src[e];
    }
}

// ---------------- GEMM: Y[RB x N] = X[RB x K] @ W[K x N], f32x2 microtiles ----------
// Threads: TY x 16. Thread (ty,tx): 8 rows (ty*8..), N/32 col-pairs at 2*tx+32*c.
template <int K, int N, int RB, int TY>
__global__ void k_gemm(const float* __restrict__ X, const float* __restrict__ W,
                       float* __restrict__ Y) {
    constexpr int CP = N / 32;
    constexpr int T  = TY * 16;
    __shared__ float xs[RB * 33];
    __shared__ float ws[32 * N];
    const int tid = threadIdx.x;
    const int tx = tid & 15, ty = tid >> 4;
    const long r0 = (long)blockIdx.x * RB;

    ull acc[8][CP];
#pragma unroll
    for (int r = 0; r < 8; r++)
#pragma unroll
        for (int c = 0; c < CP; c++) acc[r][c] = 0ull;

    for (int k0 = 0; k0 < K; k0 += 32) {
        // xs tile: RB x 32 (padded rows of 33)
        for (int t = tid; t < RB * 8; t += T) {
            int r = t >> 3, q = t & 7;
            long row = r0 + r; if (row >= N_NODES) row = N_NODES - 1;
            float4 v = __ldg((const float4*)(X + row * K + k0) + q);
            float* xp = &xs[r * 33 + q * 4];
            xp[0] = v.x; xp[1] = v.y; xp[2] = v.z; xp[3] = v.w;
        }
        // ws tile: 32 x N, contiguous slab of W
        const float4* wsrc = (const float4*)(W + (size_t)k0 * N);
        for (int t = tid; t < 8 * N; t += T)
            ((float4*)ws)[t] = __ldg(wsrc + t);
        __syncthreads();

#pragma unroll 8
        for (int kk = 0; kk < 32; kk++) {
            ull wv[CP];
#pragma unroll
            for (int c = 0; c < CP; c++)
                wv[c] = *(const ull*)&ws[kk * N + 2 * tx + 32 * c];
#pragma unroll
            for (int r = 0; r < 8; r++) {
                float xv = xs[(ty * 8 + r) * 33 + kk];
                ull xx = pack2(xv, xv);
#pragma unroll
                for (int c = 0; c < CP; c++) acc[r][c] = fma2(xx, wv[c], acc[r][c]);
            }
        }
        __syncthreads();
    }

#pragma unroll
    for (int r = 0; r < 8; r++) {
        long row = r0 + ty * 8 + r;
        if (row < N_NODES) {
#pragma unroll
            for (int c = 0; c < CP; c++) {
                float2 f = unpack2(acc[r][c]);
                *(float2*)&Y[row * N + 2 * tx + 32 * c] = f;
            }
        }
    }
}

// ---------------- pull aggregation, C=128: warp per node, lane = one float4 --------
__global__ void k_pull128(const float* __restrict__ hraw, const float* __restrict__ b,
                          float* __restrict__ out) {
    int w = (blockIdx.x * blockDim.x + threadIdx.x) >> 5;
    if (w >= N_NODES) return;
    int lane = threadIdx.x & 31;
    float din = g_dinv[w];
    float4 h0 = __ldg((const float4*)(hraw + (size_t)w * 128) + lane);
    float4 bv = __ldg((const float4*)b + lane);
    float sl = din * din;
    float4 acc;
    acc.x = fmaf(h0.x, sl, bv.x); acc.y = fmaf(h0.y, sl, bv.y);
    acc.z = fmaf(h0.z, sl, bv.z); acc.w = fmaf(h0.w, sl, bv.w);

    int s0 = g_off[w], s1 = g_off[w + 1];
    for (int j0 = s0; j0 < s1; j0 += 32) {
        int jj = j0 + lane;
        int cc = 0; float nd = 0.0f;
        if (jj < s1) { cc = g_col[jj]; nd = g_dinv[cc]; }
        int cnt = min(32, s1 - j0);
        for (int i = 0; i < cnt; i++) {
            int   s   = __shfl_sync(0xffffffffu, cc, i);
            float nrm = __shfl_sync(0xffffffffu, nd, i) * din;
            float4 hv = __ldg((const float4*)(hraw + (size_t)s * 128) + lane);
            acc.x = fmaf(hv.x, nrm, acc.x); acc.y = fmaf(hv.y, nrm, acc.y);
            acc.z = fmaf(hv.z, nrm, acc.z); acc.w = fmaf(hv.w, nrm, acc.w);
        }
    }
    // fused ReLU
    acc.x = fmaxf(acc.x, 0.0f); acc.y = fmaxf(acc.y, 0.0f);
    acc.z = fmaxf(acc.z, 0.0f); acc.w = fmaxf(acc.w, 0.0f);
    ((float4*)(out + (size_t)w * 128))[lane] = acc;
}

// ---------------- pull aggregation, C=64: warp per node, lane = one float2 ---------
__global__ void k_pull64(const float* __restrict__ hraw, const float* __restrict__ b,
                         float* __restrict__ out) {
    int w = (blockIdx.x * blockDim.x + threadIdx.x) >> 5;
    if (w >= N_NODES) return;
    int lane = threadIdx.x & 31;
    float din = g_dinv[w];
    float2 h0 = __ldg((const float2*)(hraw + (size_t)w * 64) + lane);
    float2 bv = __ldg((const float2*)b + lane);
    float sl = din * din;
    float2 acc;
    acc.x = fmaf(h0.x, sl, bv.x); acc.y = fmaf(h0.y, sl, bv.y);

    int s0 = g_off[w], s1 = g_off[w + 1];
    for (int j0 = s0; j0 < s1; j0 += 32) {
        int jj = j0 + lane;
        int cc = 0; float nd = 0.0f;
        if (jj < s1) { cc = g_col[jj]; nd = g_dinv[cc]; }
        int cnt = min(32, s1 - j0);
        for (int i = 0; i < cnt; i++) {
            int   s   = __shfl_sync(0xffffffffu, cc, i);
            float nrm = __shfl_sync(0xffffffffu, nd, i) * din;
            float2 hv = __ldg((const float2*)(hraw + (size_t)s * 64) + lane);
            acc.x = fmaf(hv.x, nrm, acc.x); acc.y = fmaf(hv.y, nrm, acc.y);
        }
    }
    ((float2*)(out + (size_t)w * 64))[lane] = acc;
}

// ---------------- launch ----------------
extern "C" void kernel_launch(void* const* d_in, const int* in_sizes, int n_in,
                              void* d_out, int out_size) {
    const float* x  = (const float*)d_in[0];
    const int*   ei = (const int*)  d_in[1];
    const float* W1 = (const float*)d_in[2];
    const float* b1 = (const float*)d_in[3];
    const float* W2 = (const float*)d_in[4];
    const float* b2 = (const float*)d_in[5];

    const int* src = ei;
    const int* dst = ei + N_EDGES;

    float* out_h2 = (float*)d_out;                       // [N, 64]
    float* out_h1 = out_h2 + (size_t)N_NODES * OUT_DIM;  // [N, 128]

    void *p_h, *p_h2;
    cudaGetSymbolAddress(&p_h,  g_h);
    cudaGetSymbolAddress(&p_h2, g_h2);
    float* hbuf  = (float*)p_h;
    float* h2buf = (float*)p_h2;

    const int TB = 256;
    const int nblk_nodes = (N_NODES + TB - 1) / TB;      // 196
    const int nblk_edges = (N_EDGES + TB - 1) / TB;

    // degrees (launches 1-3)
    k_zero <<<nblk_nodes, TB>>>();
    k_count<<<nblk_edges, TB>>>(dst);
    k_dinv <<<nblk_nodes, TB>>>();

    // GEMM1 (launch 4 — lands in the ncu capture slot)
    k_gemm<IN_DIM, HID_DIM, 64, 8><<<(N_NODES + 63) / 64, 128>>>(x, W1, hbuf);

    // CSR build (launches 5-8)
    k_scan1<<<nblk_nodes, TB>>>();
    k_scan2<<<1, TB>>>(nblk_nodes);
    k_scan3<<<nblk_nodes, TB>>>();
    k_fill <<<nblk_edges, TB>>>(src, dst);

    // layer 1 aggregation (+bias/self-loop/ReLU fused)
    k_pull128<<<(N_NODES * 32 + TB - 1) / TB, TB>>>(hbuf, b1, out_h1);

    // layer 2
    k_gemm<HID_DIM, OUT_DIM, 128, 16><<<(N_NODES + 127) / 128, 256>>>(out_h1, W2, h2buf);
    k_pull64<<<(N_NODES * 32 + TB - 1) / TB, TB>>>(h2buf, b2, out_h2);
}